// round 9
// baseline (speedup 1.0000x reference)
#include <cuda_runtime.h>
#include <cstdint>

// ---------------------------------------------------------------------------
// FeatureLevel R6 (resubmit #3; broker timeouts, never ran): spatially-sorted
// gather.
//  1) fake-quant both grids to nibble codes, x-pair packed in u64 (42MB).
//  2) counting-sort points into 1024 uv-tiles (32x32) -> taps become
//     cache-coherent: each table line fetched from DRAM once (~42MB vs ~460MB
//     of random-miss traffic measured in R1/R3).
//  3) gather processes sorted points, stores rows scattered (warp-staged).
// ---------------------------------------------------------------------------

#define R0 2048
#define R1 1024
#define CCH 8
#define QTPB 256
#define TPB 320
#define SSTRIDE 41
#define NB 1024          // 32x32 buckets
#define NPTS 2097152

__device__ unsigned long long g_pairs0[(size_t)R0 * R0];   // 33.5 MB
__device__ unsigned long long g_pairs1[(size_t)R1 * R1];   //  8.4 MB
__device__ uint4 g_spts[NPTS];                             // 33.5 MB {u,v,idx,pad}
__device__ int g_cnt[NB];
__device__ int g_cur[NB];

__device__ __forceinline__ float dq(unsigned c) {
    return fmaf((float)c, 0.0625f, -0.46875f);   // exact c/16 - 15/32
}
__device__ __forceinline__ unsigned qcode(float x) {
    float c = rintf(__fmul_rn(__fadd_rn(x, 0.46875f), 16.0f));
    c = fminf(fmaxf(c, 0.0f), 15.0f);
    return (unsigned)c;
}
__device__ __forceinline__ int bucket_of(float u, float v) {
    int bx = min(max((int)(u * 32.0f), 0), 31);
    int by = min(max((int)(v * 32.0f), 0), 31);
    return by * 32 + bx;
}

// ---- prepass: quantize + transpose + x-pair pack ----
template <int RES>
__device__ __forceinline__ unsigned pack_codes4(const float* __restrict__ g, size_t idx) {
    const size_t plane = (size_t)RES * RES;
    unsigned packed = 0;
#pragma unroll
    for (int c = 0; c < CCH; c++)
        packed |= qcode(__ldg(g + (size_t)c * plane + idx)) << (4 * c);
    return packed;
}

template <int RES>
__global__ __launch_bounds__(QTPB) void quant_pack_kernel(
    const float* __restrict__ g, unsigned long long* __restrict__ pairs) {
    size_t idx = (size_t)blockIdx.x * QTPB + threadIdx.x;
    unsigned a = pack_codes4<RES>(g, idx);
    unsigned b = __shfl_down_sync(0xFFFFFFFFu, a, 1);
    if ((threadIdx.x & 31) == 31) {
        size_t j = (idx + 1 < (size_t)RES * RES) ? idx + 1 : idx;
        b = pack_codes4<RES>(g, j);
    }
    pairs[idx] = ((unsigned long long)b << 32) | a;
}

// ---- sort pass 1: histogram (8 pts/thread, smem counters) ----
__global__ __launch_bounds__(256) void hist_kernel(const float2* __restrict__ uv, int n) {
    __shared__ int h[NB];
    for (int k = threadIdx.x; k < NB; k += 256) h[k] = 0;
    __syncthreads();
    int base = blockIdx.x * 256 * 8;
#pragma unroll
    for (int r = 0; r < 8; r++) {
        int i = base + r * 256 + threadIdx.x;
        if (i < n) {
            float2 p = __ldcs(&uv[i]);
            atomicAdd(&h[bucket_of(p.x, p.y)], 1);
        }
    }
    __syncthreads();
    for (int k = threadIdx.x; k < NB; k += 256)
        if (h[k]) atomicAdd(&g_cnt[k], h[k]);
}

// ---- sort pass 2: exclusive scan over 1024 buckets ----
__global__ __launch_bounds__(NB) void scan_kernel() {
    __shared__ int s[NB];
    int t = threadIdx.x;
    int own = g_cnt[t];
    s[t] = own;
    __syncthreads();
    for (int d = 1; d < NB; d <<= 1) {
        int x = (t >= d) ? s[t - d] : 0;
        __syncthreads();
        s[t] += x;
        __syncthreads();
    }
    g_cur[t] = s[t] - own;   // exclusive prefix
}

// ---- sort pass 3: scatter {u,v,idx} to bucket-ordered array ----
__global__ __launch_bounds__(256) void scatter_kernel(const float2* __restrict__ uv, int n) {
    int i = blockIdx.x * 256 + threadIdx.x;
    if (i >= n) return;
    float2 p = __ldcs(&uv[i]);
    int pos = atomicAdd(&g_cur[bucket_of(p.x, p.y)], 1);
    g_spts[pos] = make_uint4(__float_as_uint(p.x), __float_as_uint(p.y), (unsigned)i, 0u);
}

// ---- main gather over sorted points ----
__global__ __launch_bounds__(TPB) void gather_kernel(float* __restrict__ out, int n) {
    __shared__ float buf[TPB * SSTRIDE];
    __shared__ int sidx[TPB];
    int t = blockIdx.x * TPB + threadIdx.x;
    int wid = threadIdx.x >> 5;
    int lid = threadIdx.x & 31;

    if (t < n) {
        uint4 sp = g_spts[t];
        float u = __uint_as_float(sp.x);
        float v = __uint_as_float(sp.y);
        sidx[threadIdx.x] = (int)sp.z;
        float* row = buf + threadIdx.x * SSTRIDE;

        // G0: 4-neighbor raw gather
        float px = __fadd_rn(__fmul_rn(u, (float)R0), -0.5f);
        float py = __fadd_rn(__fmul_rn(v, (float)R0), -0.5f);
        int x0 = (int)fminf(fmaxf(floorf(px), 0.0f), (float)(R0 - 2));
        int y0 = (int)fminf(fmaxf(floorf(py), 0.0f), (float)(R0 - 2));

        unsigned long long pr0 = __ldg(&g_pairs0[(size_t)y0 * R0 + x0]);
        unsigned long long pr1 = __ldg(&g_pairs0[(size_t)(y0 + 1) * R0 + x0]);
        unsigned c00 = (unsigned)pr0, c01 = (unsigned)(pr0 >> 32);
        unsigned c10 = (unsigned)pr1, c11 = (unsigned)(pr1 >> 32);
#pragma unroll
        for (int c = 0; c < CCH; c++) {
            row[c]      = dq((c00 >> (4 * c)) & 0xFu);
            row[8 + c]  = dq((c01 >> (4 * c)) & 0xFu);
            row[16 + c] = dq((c10 >> (4 * c)) & 0xFu);
            row[24 + c] = dq((c11 >> (4 * c)) & 0xFu);
        }

        // G1: bilinear grid_sample (zeros pad), reference op order
        float gx = __fadd_rn(__fmul_rn(u, 2.0f), -1.0f);
        float gy = __fadd_rn(__fmul_rn(v, 2.0f), -1.0f);
        float ix = __fadd_rn(__fmul_rn(__fmul_rn(__fadd_rn(gx, 1.0f), 0.5f), (float)R1), -0.5f);
        float iy = __fadd_rn(__fmul_rn(__fmul_rn(__fadd_rn(gy, 1.0f), 0.5f), (float)R1), -0.5f);

        float fx0 = floorf(ix), fy0 = floorf(iy);
        float wx1 = __fadd_rn(ix, -fx0);
        float wy1 = __fadd_rn(iy, -fy0);
        float wx0 = __fadd_rn(1.0f, -wx1);
        float wy0 = __fadd_rn(1.0f, -wy1);

        int jx0 = (int)fx0, jy0 = (int)fy0;
        int jx1 = jx0 + 1, jy1 = jy0 + 1;
        bool vx0 = jx0 >= 0, vx1 = jx1 <= R1 - 1;
        bool vy0 = jy0 >= 0, vy1 = jy1 <= R1 - 1;

        float m00 = (vx0 & vy0) ? __fmul_rn(wx0, wy0) : 0.0f;
        float m10 = (vx1 & vy0) ? __fmul_rn(wx1, wy0) : 0.0f;
        float m01 = (vx0 & vy1) ? __fmul_rn(wx0, wy1) : 0.0f;
        float m11 = (vx1 & vy1) ? __fmul_rn(wx1, wy1) : 0.0f;

        int jc  = min(max(jx0, 0), R1 - 1);
        int ry0 = min(max(jy0, 0), R1 - 1);
        int ry1 = min(max(jy1, 0), R1 - 1);

        unsigned long long q0 = __ldg(&g_pairs1[(size_t)ry0 * R1 + jc]);
        unsigned long long q1 = __ldg(&g_pairs1[(size_t)ry1 * R1 + jc]);
        unsigned t00 = (unsigned)q0;
        unsigned t10 = (jx0 < 0) ? (unsigned)q0 : (unsigned)(q0 >> 32);
        unsigned t01 = (unsigned)q1;
        unsigned t11 = (jx0 < 0) ? (unsigned)q1 : (unsigned)(q1 >> 32);

#pragma unroll
        for (int c = 0; c < CCH; c++) {
            float acc = 0.0f;
            acc = fmaf(dq((t00 >> (4 * c)) & 0xFu), m00, acc);
            acc = fmaf(dq((t10 >> (4 * c)) & 0xFu), m10, acc);
            acc = fmaf(dq((t01 >> (4 * c)) & 0xFu), m01, acc);
            acc = fmaf(dq((t11 >> (4 * c)) & 0xFu), m11, acc);
            row[32 + c] = acc;
        }
    }
    __syncwarp();

    // warp-cooperative scattered row stores: each warp writes its 32 rows,
    // lanes cover the 40 floats of one row (near-coalesced 160B burst).
    int wbase = blockIdx.x * TPB + wid * 32;
    int nvalid = min(32, n - wbase);
    for (int r = 0; r < nvalid; r++) {
        int srow = wid * 32 + r;
        float* src = buf + srow * SSTRIDE;
        float* dst = out + (size_t)sidx[srow] * 40;
        __stcs(dst + lid, src[lid]);
        if (lid < 8) __stcs(dst + 32 + lid, src[32 + lid]);
    }
}

extern "C" void kernel_launch(void* const* d_in, const int* in_sizes, int n_in,
                              void* d_out, int out_size) {
    const float* uv = (const float*)d_in[0];
    const float* g0 = (const float*)d_in[1];
    const float* g1 = (const float*)d_in[2];
    float* out = (float*)d_out;

    int n = in_sizes[0] / 2;

    unsigned long long *p0, *p1;
    int* cnt;
    cudaGetSymbolAddress((void**)&p0, g_pairs0);
    cudaGetSymbolAddress((void**)&p1, g_pairs1);
    cudaGetSymbolAddress((void**)&cnt, g_cnt);

    // zero bucket counters (graph replays must be deterministic)
    cudaMemsetAsync(cnt, 0, NB * sizeof(int));

    // sort passes (independent of tables)
    hist_kernel<<<(n + 256 * 8 - 1) / (256 * 8), 256>>>((const float2*)uv, n);
    scan_kernel<<<1, NB>>>();
    scatter_kernel<<<(n + 255) / 256, 256>>>((const float2*)uv, n);

    // prepass
    quant_pack_kernel<R0><<<(R0 * R0) / QTPB, QTPB>>>(g0, p0);
    quant_pack_kernel<R1><<<(R1 * R1) / QTPB, QTPB>>>(g1, p1);

    // sorted gather
    gather_kernel<<<(n + TPB - 1) / TPB, TPB>>>(out, n);
}

// round 10
// speedup vs baseline: 2.1421x; 2.1421x over previous
#include <cuda_runtime.h>
#include <cstdint>

// ---------------------------------------------------------------------------
// FeatureLevel R10: tiled nibble-code tables, dense original-order gather.
//  - one u32 per texel (8 ch x 4-bit codes): tables 16.8 + 4.2 = 21 MB
//  - 4x4-tile storage order: one 64B atom = 4x4 texel region -> a point's
//    2x2 tap footprint touches ~1.56 atoms (vs 2.0 for row-major pairs)
//  - NO point sorting (R6 showed scattered output writes cost ~2x)
//  - output staged in smem -> dense coalesced streaming stores (R3 path)
// ---------------------------------------------------------------------------

#define R0 2048
#define R1 1024
#define CCH 8
#define QTPB 256
#define TPB 320          // multiple of 40: store index math loop-invariant
#define SSTRIDE 41       // 40 floats + 1 pad -> conflict-free smem

// Tiled code tables: tile-linear layout, 16 u32 per 4x4 tile (=64B atom).
__device__ unsigned g_codes0[(size_t)R0 * R0];   // 16.8 MB
__device__ unsigned g_codes1[(size_t)R1 * R1];   //  4.2 MB

__device__ __forceinline__ float dq(unsigned c) {
    return fmaf((float)c, 0.0625f, -0.46875f);   // exact c/16 - 15/32
}
__device__ __forceinline__ unsigned qcode(float x) {
    // codes = clip(round((x - lo)*16), 0, 15); lo = -0.46875 (exact)
    float c = rintf(__fmul_rn(__fadd_rn(x, 0.46875f), 16.0f));
    c = fminf(fmaxf(c, 0.0f), 15.0f);
    return (unsigned)c;
}

// tiled address: ((y/4)*(RES/4) + x/4)*16 + (y%4)*4 + x%4
template <int RES>
__device__ __forceinline__ unsigned taddr(int x, int y) {
    return ((unsigned)((y >> 2) * (RES >> 2) + (x >> 2)) << 4) | ((y & 3) << 2) | (x & 3);
}

// ---- prepass: quantize + transpose + tile-pack ----
// Thread t handles tile-linear slot t; decodes (x,y); reads 8 planes; packs.
template <int RES>
__global__ __launch_bounds__(QTPB) void quant_pack_kernel(
    const float* __restrict__ g, unsigned* __restrict__ codes) {
    unsigned t = blockIdx.x * QTPB + threadIdx.x;   // RES*RES % QTPB == 0
    unsigned tileIdx = t >> 4;
    unsigned within = t & 15u;
    int y = (int)((tileIdx / (RES >> 2)) * 4 + (within >> 2));
    int x = (int)((tileIdx % (RES >> 2)) * 4 + (within & 3u));
    const size_t plane = (size_t)RES * RES;
    size_t src = (size_t)y * RES + x;
    unsigned packed = 0;
#pragma unroll
    for (int c = 0; c < CCH; c++)
        packed |= qcode(__ldg(g + (size_t)c * plane + src)) << (4 * c);
    codes[t] = packed;
}

// ---- main gather: dense original order, smem-staged coalesced stores ----
__global__ __launch_bounds__(TPB) void gather_kernel(
    const float2* __restrict__ uv, float* __restrict__ out, int n) {
    __shared__ float buf[TPB * SSTRIDE];
    int i = blockIdx.x * TPB + threadIdx.x;
    int ic = min(i, n - 1);

    float2 p = __ldcs(&uv[ic]);
    float* row = buf + threadIdx.x * SSTRIDE;

    // ---------------- G0: 4-neighbor raw gather ----------------
    float px = __fadd_rn(__fmul_rn(p.x, (float)R0), -0.5f);
    float py = __fadd_rn(__fmul_rn(p.y, (float)R0), -0.5f);
    int x0 = (int)fminf(fmaxf(floorf(px), 0.0f), (float)(R0 - 2));
    int y0 = (int)fminf(fmaxf(floorf(py), 0.0f), (float)(R0 - 2));
    int x1 = x0 + 1, y1 = y0 + 1;

    unsigned c00 = __ldg(&g_codes0[taddr<R0>(x0, y0)]);
    unsigned c01 = __ldg(&g_codes0[taddr<R0>(x1, y0)]);
    unsigned c10 = __ldg(&g_codes0[taddr<R0>(x0, y1)]);
    unsigned c11 = __ldg(&g_codes0[taddr<R0>(x1, y1)]);
#pragma unroll
    for (int c = 0; c < CCH; c++) {
        row[c]      = dq((c00 >> (4 * c)) & 0xFu);
        row[8 + c]  = dq((c01 >> (4 * c)) & 0xFu);
        row[16 + c] = dq((c10 >> (4 * c)) & 0xFu);
        row[24 + c] = dq((c11 >> (4 * c)) & 0xFu);
    }

    // ---------------- G1: bilinear grid_sample (zeros pad) ----------------
    // Reference op order exactly (no FMA contraction in index math).
    float gx = __fadd_rn(__fmul_rn(p.x, 2.0f), -1.0f);
    float gy = __fadd_rn(__fmul_rn(p.y, 2.0f), -1.0f);
    float ix = __fadd_rn(__fmul_rn(__fmul_rn(__fadd_rn(gx, 1.0f), 0.5f), (float)R1), -0.5f);
    float iy = __fadd_rn(__fmul_rn(__fmul_rn(__fadd_rn(gy, 1.0f), 0.5f), (float)R1), -0.5f);

    float fx0 = floorf(ix), fy0 = floorf(iy);
    float wx1 = __fadd_rn(ix, -fx0);
    float wy1 = __fadd_rn(iy, -fy0);
    float wx0 = __fadd_rn(1.0f, -wx1);
    float wy0 = __fadd_rn(1.0f, -wy1);

    int jx0 = (int)fx0, jy0 = (int)fy0;
    int jx1 = jx0 + 1, jy1 = jy0 + 1;
    bool vx0 = jx0 >= 0, vx1 = jx1 <= R1 - 1;
    bool vy0 = jy0 >= 0, vy1 = jy1 <= R1 - 1;

    float m00 = (vx0 & vy0) ? __fmul_rn(wx0, wy0) : 0.0f;
    float m10 = (vx1 & vy0) ? __fmul_rn(wx1, wy0) : 0.0f;
    float m01 = (vx0 & vy1) ? __fmul_rn(wx0, wy1) : 0.0f;
    float m11 = (vx1 & vy1) ? __fmul_rn(wx1, wy1) : 0.0f;

    // clamp all coords; masks zero out the invalid taps
    int cx0 = min(max(jx0, 0), R1 - 1), cx1 = min(max(jx1, 0), R1 - 1);
    int cy0 = min(max(jy0, 0), R1 - 1), cy1 = min(max(jy1, 0), R1 - 1);

    unsigned t00 = __ldg(&g_codes1[taddr<R1>(cx0, cy0)]);
    unsigned t10 = __ldg(&g_codes1[taddr<R1>(cx1, cy0)]);
    unsigned t01 = __ldg(&g_codes1[taddr<R1>(cx0, cy1)]);
    unsigned t11 = __ldg(&g_codes1[taddr<R1>(cx1, cy1)]);

#pragma unroll
    for (int c = 0; c < CCH; c++) {
        float acc = 0.0f;
        acc = fmaf(dq((t00 >> (4 * c)) & 0xFu), m00, acc);
        acc = fmaf(dq((t10 >> (4 * c)) & 0xFu), m10, acc);
        acc = fmaf(dq((t01 >> (4 * c)) & 0xFu), m01, acc);
        acc = fmaf(dq((t11 >> (4 * c)) & 0xFu), m11, acc);
        row[32 + c] = acc;
    }

    __syncthreads();

    // ---------------- dense coalesced streaming store ----------------
    int tq = threadIdx.x / 40;
    int cc = threadIdx.x - tq * 40;
    size_t base = (size_t)blockIdx.x * TPB * 40 + threadIdx.x;
    size_t total = (size_t)n * 40;
#pragma unroll
    for (int k = 0; k < 40; k++) {
        int pp = 8 * k + tq;
        size_t g = base + (size_t)k * TPB;
        if (g < total) __stcs(out + g, buf[pp * SSTRIDE + cc]);
    }
}

extern "C" void kernel_launch(void* const* d_in, const int* in_sizes, int n_in,
                              void* d_out, int out_size) {
    const float* uv = (const float*)d_in[0];
    const float* g0 = (const float*)d_in[1];
    const float* g1 = (const float*)d_in[2];
    float* out = (float*)d_out;

    int n = in_sizes[0] / 2;

    unsigned *p0, *p1;
    cudaGetSymbolAddress((void**)&p0, g_codes0);
    cudaGetSymbolAddress((void**)&p1, g_codes1);

    quant_pack_kernel<R0><<<(R0 * R0) / QTPB, QTPB>>>(g0, p0);
    quant_pack_kernel<R1><<<(R1 * R1) / QTPB, QTPB>>>(g1, p1);

    gather_kernel<<<(n + TPB - 1) / TPB, TPB>>>((const float2*)uv, out, n);
}

// round 17
// speedup vs baseline: 2.1688x; 1.0125x over previous
#include <cuda_runtime.h>
#include <cstdint>

// ---------------------------------------------------------------------------
// FeatureLevel R15 (resubmit #2; broker timeouts, never ran):
// tiled nibble-code tables + L2 eviction-priority control via access-policy
// (createpolicy + cache_hint) — the scalar-width-legal form
// (R14 showed inline .L2::evict_last requires 256-bit accesses on sm_103a).
//  - one u32 per texel (8ch x 4-bit), 4x4-tile order (64B atom = 4x4 texels)
//    tables: 16.8 + 4.2 = 21 MB (fits easily in 126MB L2)
//  - table writes + tap reads carry an L2::evict_last policy -> stay resident
//  - output uses streaming (evict-first) stores -> doesn't evict tables
//  - both quant_pack passes fused into one launch
// ---------------------------------------------------------------------------

#define R0 2048
#define R1 1024
#define CCH 8
#define QTPB 256
#define TPB 320          // multiple of 40: store index math loop-invariant
#define SSTRIDE 41       // 40 floats + 1 pad -> conflict-free smem

__device__ unsigned g_codes0[(size_t)R0 * R0];   // 16.8 MB
__device__ unsigned g_codes1[(size_t)R1 * R1];   //  4.2 MB

__device__ __forceinline__ float dq(unsigned c) {
    return fmaf((float)c, 0.0625f, -0.46875f);   // exact c/16 - 15/32
}
__device__ __forceinline__ unsigned qcode(float x) {
    float c = rintf(__fmul_rn(__fadd_rn(x, 0.46875f), 16.0f));
    c = fminf(fmaxf(c, 0.0f), 15.0f);
    return (unsigned)c;
}

// L2 evict_last access policy (fraction = 1.0 -> whole policy window last)
__device__ __forceinline__ unsigned long long mk_evict_last() {
    unsigned long long pol;
    asm("createpolicy.fractional.L2::evict_last.b64 %0, 1.0;" : "=l"(pol));
    return pol;
}
__device__ __forceinline__ unsigned ld_tab(const unsigned* p, unsigned long long pol) {
    unsigned v;
    asm volatile("ld.global.nc.L2::cache_hint.u32 %0, [%1], %2;"
                 : "=r"(v) : "l"(p), "l"(pol));
    return v;
}
__device__ __forceinline__ void st_tab(unsigned* p, unsigned v, unsigned long long pol) {
    asm volatile("st.global.L2::cache_hint.u32 [%0], %1, %2;"
                 :: "l"(p), "r"(v), "l"(pol));
}

// tiled address: ((y/4)*(RES/4) + x/4)*16 + (y%4)*4 + x%4
template <int RES>
__device__ __forceinline__ unsigned taddr(int x, int y) {
    return ((unsigned)((y >> 2) * (RES >> 2) + (x >> 2)) << 4) | ((y & 3) << 2) | (x & 3);
}

// ---- fused prepass: quantize + transpose + tile-pack both grids ----
template <int RES>
__device__ __forceinline__ void quant_one(const float* __restrict__ g,
                                          unsigned* __restrict__ codes, unsigned t,
                                          unsigned long long pol) {
    unsigned tileIdx = t >> 4;
    unsigned within = t & 15u;
    int y = (int)((tileIdx / (RES >> 2)) * 4 + (within >> 2));
    int x = (int)((tileIdx % (RES >> 2)) * 4 + (within & 3u));
    const size_t plane = (size_t)RES * RES;
    size_t src = (size_t)y * RES + x;
    unsigned packed = 0;
#pragma unroll
    for (int c = 0; c < CCH; c++)
        packed |= qcode(__ldg(g + (size_t)c * plane + src)) << (4 * c);
    st_tab(codes + t, packed, pol);
}

__global__ __launch_bounds__(QTPB) void quant_pack_fused_kernel(
    const float* __restrict__ g0, const float* __restrict__ g1,
    unsigned* __restrict__ codes0, unsigned* __restrict__ codes1) {
    unsigned t = blockIdx.x * QTPB + threadIdx.x;
    unsigned long long pol = mk_evict_last();
    const unsigned N0 = (unsigned)R0 * R0;
    if (t < N0) quant_one<R0>(g0, codes0, t, pol);
    else        quant_one<R1>(g1, codes1, t - N0, pol);
}

// ---- main gather: dense original order, smem-staged coalesced stores ----
__global__ __launch_bounds__(TPB) void gather_kernel(
    const float2* __restrict__ uv, float* __restrict__ out, int n) {
    __shared__ float buf[TPB * SSTRIDE];
    int i = blockIdx.x * TPB + threadIdx.x;
    int ic = min(i, n - 1);
    unsigned long long pol = mk_evict_last();

    float2 p = __ldcs(&uv[ic]);
    float* row = buf + threadIdx.x * SSTRIDE;

    // ---------------- G0: 4-neighbor raw gather ----------------
    float px = __fadd_rn(__fmul_rn(p.x, (float)R0), -0.5f);
    float py = __fadd_rn(__fmul_rn(p.y, (float)R0), -0.5f);
    int x0 = (int)fminf(fmaxf(floorf(px), 0.0f), (float)(R0 - 2));
    int y0 = (int)fminf(fmaxf(floorf(py), 0.0f), (float)(R0 - 2));
    int x1 = x0 + 1, y1 = y0 + 1;

    unsigned c00 = ld_tab(&g_codes0[taddr<R0>(x0, y0)], pol);
    unsigned c01 = ld_tab(&g_codes0[taddr<R0>(x1, y0)], pol);
    unsigned c10 = ld_tab(&g_codes0[taddr<R0>(x0, y1)], pol);
    unsigned c11 = ld_tab(&g_codes0[taddr<R0>(x1, y1)], pol);
#pragma unroll
    for (int c = 0; c < CCH; c++) {
        row[c]      = dq((c00 >> (4 * c)) & 0xFu);
        row[8 + c]  = dq((c01 >> (4 * c)) & 0xFu);
        row[16 + c] = dq((c10 >> (4 * c)) & 0xFu);
        row[24 + c] = dq((c11 >> (4 * c)) & 0xFu);
    }

    // ---------------- G1: bilinear grid_sample (zeros pad) ----------------
    // Reference op order exactly (no FMA contraction in index math).
    float gx = __fadd_rn(__fmul_rn(p.x, 2.0f), -1.0f);
    float gy = __fadd_rn(__fmul_rn(p.y, 2.0f), -1.0f);
    float ix = __fadd_rn(__fmul_rn(__fmul_rn(__fadd_rn(gx, 1.0f), 0.5f), (float)R1), -0.5f);
    float iy = __fadd_rn(__fmul_rn(__fmul_rn(__fadd_rn(gy, 1.0f), 0.5f), (float)R1), -0.5f);

    float fx0 = floorf(ix), fy0 = floorf(iy);
    float wx1 = __fadd_rn(ix, -fx0);
    float wy1 = __fadd_rn(iy, -fy0);
    float wx0 = __fadd_rn(1.0f, -wx1);
    float wy0 = __fadd_rn(1.0f, -wy1);

    int jx0 = (int)fx0, jy0 = (int)fy0;
    int jx1 = jx0 + 1, jy1 = jy0 + 1;
    bool vx0 = jx0 >= 0, vx1 = jx1 <= R1 - 1;
    bool vy0 = jy0 >= 0, vy1 = jy1 <= R1 - 1;

    float m00 = (vx0 & vy0) ? __fmul_rn(wx0, wy0) : 0.0f;
    float m10 = (vx1 & vy0) ? __fmul_rn(wx1, wy0) : 0.0f;
    float m01 = (vx0 & vy1) ? __fmul_rn(wx0, wy1) : 0.0f;
    float m11 = (vx1 & vy1) ? __fmul_rn(wx1, wy1) : 0.0f;

    int cx0 = min(max(jx0, 0), R1 - 1), cx1 = min(max(jx1, 0), R1 - 1);
    int cy0 = min(max(jy0, 0), R1 - 1), cy1 = min(max(jy1, 0), R1 - 1);

    unsigned t00 = ld_tab(&g_codes1[taddr<R1>(cx0, cy0)], pol);
    unsigned t10 = ld_tab(&g_codes1[taddr<R1>(cx1, cy0)], pol);
    unsigned t01 = ld_tab(&g_codes1[taddr<R1>(cx0, cy1)], pol);
    unsigned t11 = ld_tab(&g_codes1[taddr<R1>(cx1, cy1)], pol);

#pragma unroll
    for (int c = 0; c < CCH; c++) {
        float acc = 0.0f;
        acc = fmaf(dq((t00 >> (4 * c)) & 0xFu), m00, acc);
        acc = fmaf(dq((t10 >> (4 * c)) & 0xFu), m10, acc);
        acc = fmaf(dq((t01 >> (4 * c)) & 0xFu), m01, acc);
        acc = fmaf(dq((t11 >> (4 * c)) & 0xFu), m11, acc);
        row[32 + c] = acc;
    }

    __syncthreads();

    // ---------------- dense coalesced streaming store ----------------
    int tq = threadIdx.x / 40;
    int cc = threadIdx.x - tq * 40;
    size_t base = (size_t)blockIdx.x * TPB * 40 + threadIdx.x;
    size_t total = (size_t)n * 40;
#pragma unroll
    for (int k = 0; k < 40; k++) {
        int pp = 8 * k + tq;
        size_t g = base + (size_t)k * TPB;
        if (g < total) __stcs(out + g, buf[pp * SSTRIDE + cc]);
    }
}

extern "C" void kernel_launch(void* const* d_in, const int* in_sizes, int n_in,
                              void* d_out, int out_size) {
    const float* uv = (const float*)d_in[0];
    const float* g0 = (const float*)d_in[1];
    const float* g1 = (const float*)d_in[2];
    float* out = (float*)d_out;

    int n = in_sizes[0] / 2;

    unsigned *p0, *p1;
    cudaGetSymbolAddress((void**)&p0, g_codes0);
    cudaGetSymbolAddress((void**)&p1, g_codes1);

    const unsigned NTOT = (unsigned)R0 * R0 + (unsigned)R1 * R1;   // % QTPB == 0
    quant_pack_fused_kernel<<<NTOT / QTPB, QTPB>>>(g0, g1, p0, p1);

    gather_kernel<<<(n + TPB - 1) / TPB, TPB>>>((const float2*)uv, out, n);
}